// round 1
// baseline (speedup 1.0000x reference)
#include <cuda_runtime.h>
#include <cuda_fp16.h>
#include <cstdint>

// ---------------- problem constants ----------------
#define CCH   512               // C_IN = C_OUT
#define NB    16                // batch
#define HW    64                // H = W
#define NPIX  4096              // 64*64
#define KTAP  9
#define STYLE_SCALE 0.04419417382415922f   // 1/sqrt(512)
#define CONV_SCALE  0.014731391274719742f  // 1/sqrt(512*9)
#define EPSV  1e-6f

// ---------------- device scratch (allowed: __device__ globals) ----------------
__device__ float  g_s[NB * CCH];                 // scaled style: s * CONV_SCALE
__device__ float  g_sigma[NB * CCH];
__device__ float  g_cwt[KTAP * CCH * CCH];       // conv_weight transposed [t][ic][oc]
__device__ float  g_q[CCH * CCH];                // q[ic][oc] = sum_t cw^2
__device__ __half g_wmod[(size_t)NB * KTAP * CCH * CCH];   // [b][t][ic][oc] fp16 (75.5MB)
__device__ __half g_xp[(size_t)NB * 66 * 66 * CCH];        // padded NHWC fp16 (71.4MB)

// ---------------- small prep kernels ----------------
__global__ void k_style(const float* __restrict__ w, const float* __restrict__ sw,
                        const float* __restrict__ sb) {
    int b = blockIdx.x, i = threadIdx.x;
    __shared__ float wb[CCH];
    wb[i] = w[b * CCH + i];
    __syncthreads();
    const float* row = sw + (size_t)i * CCH;
    float acc = 0.f;
#pragma unroll 8
    for (int j = 0; j < CCH; j++) acc += row[j] * wb[j];
    g_s[b * CCH + i] = (acc * STYLE_SCALE + sb[i]) * CONV_SCALE;
}

__global__ void k_cwt(const float* __restrict__ cw) {
    int oc = blockIdx.x;
    const float* src = cw + (size_t)oc * CCH * KTAP;
    for (int e = threadIdx.x; e < CCH * KTAP; e += blockDim.x) {
        int ic = e / 9, t = e - ic * 9;
        g_cwt[((size_t)t * CCH + ic) * CCH + oc] = src[e];
    }
}

__global__ void k_q() {
    int ic = blockIdx.x, oc = threadIdx.x;
    float a = 0.f;
#pragma unroll
    for (int t = 0; t < KTAP; t++) {
        float v = g_cwt[((size_t)t * CCH + ic) * CCH + oc];
        a += v * v;
    }
    g_q[ic * CCH + oc] = a;
}

__global__ void k_sigma() {
    int b = blockIdx.x, oc = threadIdx.x;
    __shared__ float s2[CCH];
    float sv = g_s[b * CCH + oc];
    s2[oc] = sv * sv;
    __syncthreads();
    float a = 0.f;
    for (int ic = 0; ic < CCH; ic++) a += s2[ic] * g_q[ic * CCH + oc];
    g_sigma[b * CCH + oc] = rsqrtf(a + EPSV);
}

__global__ void k_wmod() {
    int bid = blockIdx.x;                 // b*4608 + t*512 + ic
    int b = bid / (KTAP * CCH);
    int rem = bid - b * (KTAP * CCH);     // t*512 + ic
    int ic = rem & (CCH - 1);
    int oc = threadIdx.x;
    float v = g_cwt[(size_t)rem * CCH + oc] * g_s[b * CCH + ic] * g_sigma[b * CCH + oc];
    g_wmod[((size_t)b * (KTAP * CCH) + rem) * CCH + oc] = __float2half_rn(v);
}

__global__ void k_zero_xp() {
    const size_t n4 = (size_t)NB * 66 * 66 * CCH * sizeof(__half) / 16;
    uint4 z = make_uint4(0, 0, 0, 0);
    for (size_t i = (size_t)blockIdx.x * blockDim.x + threadIdx.x; i < n4;
         i += (size_t)gridDim.x * blockDim.x)
        ((uint4*)g_xp)[i] = z;
}

// NCHW fp32 -> padded NHWC fp16 (interior only; borders stay zero)
__global__ void k_xpose(const float* __restrict__ x) {
    int b = blockIdx.x >> 6;
    int h = blockIdx.x & 63;
    __shared__ float tile[32][65];
    const float* xsrc = x + ((size_t)b * CCH) * NPIX + (size_t)h * HW;
    __half* dst = g_xp + (((size_t)b * 66 + h + 1) * 66 + 1) * CCH;
    for (int ic0 = 0; ic0 < CCH; ic0 += 32) {
        __syncthreads();
        for (int e = threadIdx.x; e < 32 * 64; e += 256) {
            int icl = e >> 6, wx = e & 63;
            tile[icl][wx] = xsrc[(size_t)(ic0 + icl) * NPIX + wx];
        }
        __syncthreads();
        for (int e = threadIdx.x; e < 64 * 16; e += 256) {
            int wx = e >> 4, pr = e & 15;
            __half2 hv = __floats2half2_rn(tile[pr * 2][wx], tile[pr * 2 + 1][wx]);
            *(__half2*)(dst + (size_t)wx * CCH + ic0 + pr * 2) = hv;
        }
    }
}

// ---------------- mma / ldmatrix / cp.async helpers ----------------
__device__ __forceinline__ void mma16816(float* c, const uint32_t* a, uint32_t b0, uint32_t b1) {
    asm volatile(
        "mma.sync.aligned.m16n8k16.row.col.f32.f16.f16.f32 "
        "{%0,%1,%2,%3}, {%4,%5,%6,%7}, {%8,%9}, {%0,%1,%2,%3};\n"
        : "+f"(c[0]), "+f"(c[1]), "+f"(c[2]), "+f"(c[3])
        : "r"(a[0]), "r"(a[1]), "r"(a[2]), "r"(a[3]), "r"(b0), "r"(b1));
}
__device__ __forceinline__ void ldsm_x4(uint32_t* r, uint32_t addr) {
    asm volatile("ldmatrix.sync.aligned.m8n8.x4.shared.b16 {%0,%1,%2,%3}, [%4];\n"
                 : "=r"(r[0]), "=r"(r[1]), "=r"(r[2]), "=r"(r[3]) : "r"(addr));
}
__device__ __forceinline__ void ldsm_x2_t(uint32_t& r0, uint32_t& r1, uint32_t addr) {
    asm volatile("ldmatrix.sync.aligned.m8n8.x2.trans.shared.b16 {%0,%1}, [%2];\n"
                 : "=r"(r0), "=r"(r1) : "r"(addr));
}
__device__ __forceinline__ void cpa16(uint32_t dst, const void* src) {
    asm volatile("cp.async.cg.shared.global [%0], [%1], 16;\n" :: "r"(dst), "l"(src));
}
#define CP_COMMIT() asm volatile("cp.async.commit_group;\n" ::: "memory")
#define CP_WAIT0()  asm volatile("cp.async.wait_group 0;\n" ::: "memory")

// ---------------- main conv kernel ----------------
// CTA tile: M = 128 pixels (2 image rows), N = 128 output channels.
// Xs: [4 rows][66 cols][64 ic + 8 pad] halfs, Bs: 2 x [64 ic][128 oc + 8 pad].
#define XS_STRIDE_H 72
#define XS_HALFS    (264 * XS_STRIDE_H)     // 19008
#define BS_STRIDE_H 136
#define BS_HALFS    (64 * BS_STRIDE_H)      // 8704 per buffer
#define SMEM_BYTES  ((XS_HALFS + 2 * BS_HALFS) * 2)   // 72832

__global__ void __launch_bounds__(256, 2)
k_conv(const float* __restrict__ noise, const float* __restrict__ nzw,
       const float* __restrict__ bias, float* __restrict__ out) {
    extern __shared__ __half smemh[];
    uint32_t xs_b = (uint32_t)__cvta_generic_to_shared(smemh);
    uint32_t bs_b = xs_b + XS_HALFS * 2;

    const int b = blockIdx.z, mt = blockIdx.y, nt = blockIdx.x;
    const int tid = threadIdx.x, lane = tid & 31, wid = tid >> 5;
    const int warp_m = wid & 1;      // image row within tile (py)
    const int warp_n = wid >> 1;     // 32-oc slab
    const int y0 = mt * 2;

    const __half* xp_b = g_xp + (((size_t)b * 66 + y0) * 66) * CCH;
    const __half* wm_b = g_wmod + (size_t)b * KTAP * CCH * CCH + (size_t)nt * 128;

    float acc[4][4][4];
#pragma unroll
    for (int i = 0; i < 4; i++)
#pragma unroll
        for (int j = 0; j < 4; j++)
#pragma unroll
            for (int k = 0; k < 4; k++) acc[i][j][k] = 0.f;

    const int off_m = ((lane >> 3) & 1) * 8 + (lane & 7);   // A ldmatrix row-in-frag
    const int off_k = (lane >> 4) * 8;                      // A ldmatrix k-block
    const uint32_t b_row = bs_b + (uint32_t)((lane & 15) * BS_STRIDE_H + warp_n * 32) * 2;

    for (int kc = 0; kc < 8; kc++) {
        __syncthreads();
        // load X chunk: 264 rows (4 img-rows x 66 cols) x 64 ic
        {
            const __half* src = xp_b + kc * 64;
            for (int s = tid; s < 264 * 8; s += 256) {
                int row = s >> 3, seg = s & 7;
                cpa16(xs_b + (uint32_t)(row * 144 + seg * 16),
                      src + (size_t)row * CCH + seg * 8);
            }
        }
        // load B chunk for tap 0 into buffer 0
        {
            const __half* src = wm_b + ((size_t)kc * 64) * CCH;   // t = 0
            for (int s = tid; s < 64 * 16; s += 256) {
                int row = s >> 4, seg = s & 15;
                cpa16(bs_b + (uint32_t)(row * 272 + seg * 16),
                      src + (size_t)row * CCH + seg * 8);
            }
        }
        CP_COMMIT();
        CP_WAIT0();
        __syncthreads();

        for (int t = 0; t < KTAP; t++) {
            int buf = t & 1;
            if (t < 8) {   // prefetch next tap's weights into other buffer
                const __half* src = wm_b + (((size_t)(t + 1) * CCH) + kc * 64) * CCH;
                uint32_t dstb = bs_b + (uint32_t)((buf ^ 1) * BS_HALFS * 2);
                for (int s = tid; s < 64 * 16; s += 256) {
                    int row = s >> 4, seg = s & 15;
                    cpa16(dstb + (uint32_t)(row * 272 + seg * 16),
                          src + (size_t)row * CCH + seg * 8);
                }
                CP_COMMIT();
            }

            int dy = t / 3, dx = t - dy * 3;
            uint32_t A0 = xs_b +
                (uint32_t)((((warp_m + dy) * 66) + off_m + dx) * 144 + off_k * 2);
            uint32_t Bb = b_row + (uint32_t)(buf * BS_HALFS * 2);

#pragma unroll
            for (int k16 = 0; k16 < 4; k16++) {
                uint32_t a[4][4];
#pragma unroll
                for (int mf = 0; mf < 4; mf++)
                    ldsm_x4(a[mf], A0 + mf * 2304 + k16 * 32);
#pragma unroll
                for (int nf = 0; nf < 4; nf++) {
                    uint32_t b0, b1;
                    ldsm_x2_t(b0, b1, Bb + k16 * (16 * 272) + nf * 16);
#pragma unroll
                    for (int mf = 0; mf < 4; mf++)
                        mma16816(acc[mf][nf], a[mf], b0, b1);
                }
            }

            if (t < 8) { CP_WAIT0(); __syncthreads(); }
        }
    }

    // -------- epilogue: + noise_weight*noise + bias, leaky relu 0.2 --------
    const int g = lane >> 2, tq = lane & 3;
    const int yrow = y0 + warp_m;
    const float* nrow = noise + (size_t)b * NPIX + (size_t)yrow * HW;
    float nzv[4][2];
#pragma unroll
    for (int mf = 0; mf < 4; mf++) {
        nzv[mf][0] = nrow[mf * 16 + g];
        nzv[mf][1] = nrow[mf * 16 + g + 8];
    }
    const size_t outb = (size_t)b * CCH * NPIX;
#pragma unroll
    for (int nf = 0; nf < 4; nf++) {
        int oc = nt * 128 + warp_n * 32 + nf * 8 + tq * 2;
        float nw0 = nzw[oc], nw1 = nzw[oc + 1];
        float bi0 = bias[oc], bi1 = bias[oc + 1];
        float* o0 = out + outb + (size_t)oc * NPIX + (size_t)yrow * HW;
#pragma unroll
        for (int mf = 0; mf < 4; mf++) {
            int x0 = mf * 16 + g;
            float v;
            v = acc[mf][nf][0] + nw0 * nzv[mf][0] + bi0; o0[x0]            = v > 0.f ? v : 0.2f * v;
            v = acc[mf][nf][1] + nw1 * nzv[mf][0] + bi1; o0[NPIX + x0]     = v > 0.f ? v : 0.2f * v;
            v = acc[mf][nf][2] + nw0 * nzv[mf][1] + bi0; o0[x0 + 8]        = v > 0.f ? v : 0.2f * v;
            v = acc[mf][nf][3] + nw1 * nzv[mf][1] + bi1; o0[NPIX + x0 + 8] = v > 0.f ? v : 0.2f * v;
        }
    }
}

// ---------------- launcher ----------------
extern "C" void kernel_launch(void* const* d_in, const int* in_sizes, int n_in,
                              void* d_out, int out_size) {
    const float* x     = (const float*)d_in[0];
    const float* w     = (const float*)d_in[1];
    const float* sw    = (const float*)d_in[2];
    const float* sb    = (const float*)d_in[3];
    const float* cw    = (const float*)d_in[4];
    const float* nzw   = (const float*)d_in[5];
    const float* bias  = (const float*)d_in[6];
    const float* noise = (const float*)d_in[7];
    float* out = (float*)d_out;

    cudaFuncSetAttribute((const void*)k_conv,
                         cudaFuncAttributeMaxDynamicSharedMemorySize, SMEM_BYTES);

    k_style<<<NB, CCH>>>(w, sw, sb);
    k_cwt<<<CCH, 256>>>(cw);
    k_q<<<CCH, CCH>>>();
    k_sigma<<<NB, CCH>>>();
    k_wmod<<<NB * KTAP * CCH, CCH>>>();
    k_zero_xp<<<2048, 256>>>();
    k_xpose<<<NB * HW, 256>>>(x);
    k_conv<<<dim3(4, 32, NB), 256, SMEM_BYTES>>>(noise, nzw, bias, out);
}

// round 3
// speedup vs baseline: 1.3443x; 1.3443x over previous
#include <cuda_runtime.h>
#include <cuda_fp16.h>
#include <cstdint>

// ---------------- problem constants ----------------
#define CCH   512
#define NB    16
#define HW    64
#define NPIX  4096
#define KTAP  9
#define STYLE_SCALE 0.04419417382415922f   // 1/sqrt(512)
#define CONV_SCALE  0.014731391274719742f  // 1/sqrt(512*9)
#define EPSV  1e-6f

// ---------------- device scratch ----------------
__device__ float  g_s[NB * CCH];                     // style * CONV_SCALE
__device__ float  g_sigma[NB * CCH];
__device__ float  g_cwt[KTAP * CCH * CCH];           // [t][ic][oc]
__device__ float  g_q2[CCH * CCH];                   // [oc][ic] = sum_t cw^2
__device__ __half g_wmod[(size_t)NB * KTAP * CCH * CCH];   // [b][t][ic][oc]
__device__ __half g_xp[(size_t)NB * 66 * 66 * CCH];        // padded NHWC fp16

// ---------------- prep kernels ----------------
// style: one warp per (b, i)
__global__ void k_style(const float* __restrict__ w, const float* __restrict__ sw,
                        const float* __restrict__ sb) {
    int gw = (blockIdx.x * blockDim.x + threadIdx.x) >> 5;
    int lane = threadIdx.x & 31;
    if (gw >= NB * CCH) return;
    int b = gw >> 9, i = gw & 511;
    const float* row = sw + (size_t)i * CCH;
    const float* wb = w + b * CCH;
    float acc = 0.f;
#pragma unroll 4
    for (int j = lane; j < CCH; j += 32) acc += row[j] * wb[j];
#pragma unroll
    for (int o = 16; o; o >>= 1) acc += __shfl_xor_sync(0xFFFFFFFFu, acc, o);
    if (lane == 0) g_s[b * CCH + i] = (acc * STYLE_SCALE + sb[i]) * CONV_SCALE;
}

// cw [oc][ic][t] -> cwt [t][ic][oc] + q2 [oc][ic], all-coalesced via smem tiles
__global__ void k_prepw(const float* __restrict__ cw) {
    __shared__ float tl[KTAP][32][33];
    int ic0 = blockIdx.x * 32, oc0 = blockIdx.y * 32;
    int tx = threadIdx.x, ty = threadIdx.y;
#pragma unroll
    for (int r = 0; r < 4; r++) {
        int ocl = ty + 8 * r;
        const float* src = cw + ((size_t)(oc0 + ocl) * CCH + ic0 + tx) * KTAP;
#pragma unroll
        for (int t = 0; t < KTAP; t++) tl[t][ocl][tx] = src[t];
    }
    __syncthreads();
#pragma unroll
    for (int t = 0; t < KTAP; t++)
#pragma unroll
        for (int r = 0; r < 4; r++) {
            int icl = ty + 8 * r;
            g_cwt[((size_t)t * CCH + ic0 + icl) * CCH + oc0 + tx] = tl[t][tx][icl];
        }
#pragma unroll
    for (int r = 0; r < 4; r++) {
        int ocl = ty + 8 * r;
        float a = 0.f;
#pragma unroll
        for (int t = 0; t < KTAP; t++) {
            float v = tl[t][ocl][tx];
            a += v * v;
        }
        g_q2[(size_t)(oc0 + ocl) * CCH + ic0 + tx] = a;
    }
}

// sigma: one warp per (b, oc)
__global__ void k_sigma() {
    int gw = (blockIdx.x * blockDim.x + threadIdx.x) >> 5;
    int lane = threadIdx.x & 31;
    if (gw >= NB * CCH) return;
    int b = gw >> 9, oc = gw & 511;
    const float* q = g_q2 + (size_t)oc * CCH;
    const float* s = g_s + b * CCH;
    float a = 0.f;
#pragma unroll 4
    for (int j = lane; j < CCH; j += 32) {
        float sv = s[j];
        a += sv * sv * q[j];
    }
#pragma unroll
    for (int o = 16; o; o >>= 1) a += __shfl_xor_sync(0xFFFFFFFFu, a, o);
    if (lane == 0) g_sigma[b * CCH + oc] = rsqrtf(a + EPSV);
}

// modulated weights [b][t][ic][oc] fp16; block=(b,ic), loop t
__global__ void k_wmod() {
    int bid = blockIdx.x;
    int b = bid >> 9, ic = bid & 511;
    int oc = threadIdx.x;
    float sv = g_s[b * CCH + ic];
    float sg = g_sigma[b * CCH + oc];
    float f = sv * sg;
#pragma unroll
    for (int t = 0; t < KTAP; t++) {
        float v = g_cwt[((size_t)t * CCH + ic) * CCH + oc] * f;
        g_wmod[(((size_t)b * KTAP + t) * CCH + ic) * CCH + oc] = __float2half_rn(v);
    }
}

// zero only padded borders of xp
__global__ void k_borders() {
    int b = blockIdx.y, r = blockIdx.x;
    int y, x;
    if (r < 66)       { y = 0;       x = r; }
    else if (r < 132) { y = 65;      x = r - 66; }
    else if (r < 196) { y = r - 131; x = 0; }
    else              { y = r - 195; x = 65; }
    uint2* p = (uint2*)(g_xp + (((size_t)b * 66 + y) * 66 + x) * CCH);
    p[threadIdx.x] = make_uint2(0, 0);
}

// NCHW fp32 -> padded NHWC fp16 (interior)
__global__ void k_xpose(const float* __restrict__ x) {
    int b = blockIdx.x >> 6;
    int h = blockIdx.x & 63;
    __shared__ float tile[32][65];
    const float* xsrc = x + ((size_t)b * CCH) * NPIX + (size_t)h * HW;
    __half* dst = g_xp + (((size_t)b * 66 + h + 1) * 66 + 1) * CCH;
    for (int ic0 = 0; ic0 < CCH; ic0 += 32) {
        __syncthreads();
        for (int e = threadIdx.x; e < 32 * 64; e += 256) {
            int icl = e >> 6, wx = e & 63;
            tile[icl][wx] = xsrc[(size_t)(ic0 + icl) * NPIX + wx];
        }
        __syncthreads();
        for (int e = threadIdx.x; e < 64 * 16; e += 256) {
            int wx = e >> 4, pr = e & 15;
            __half2 hv = __floats2half2_rn(tile[pr * 2][wx], tile[pr * 2 + 1][wx]);
            *(__half2*)(dst + (size_t)wx * CCH + ic0 + pr * 2) = hv;
        }
    }
}

// ---------------- mma / ldmatrix / cp.async helpers ----------------
__device__ __forceinline__ void mma16816(float* c, const uint32_t* a, uint32_t b0, uint32_t b1) {
    asm volatile(
        "mma.sync.aligned.m16n8k16.row.col.f32.f16.f16.f32 "
        "{%0,%1,%2,%3}, {%4,%5,%6,%7}, {%8,%9}, {%0,%1,%2,%3};\n"
        : "+f"(c[0]), "+f"(c[1]), "+f"(c[2]), "+f"(c[3])
        : "r"(a[0]), "r"(a[1]), "r"(a[2]), "r"(a[3]), "r"(b0), "r"(b1));
}
__device__ __forceinline__ void ldsm_x4(uint32_t* r, uint32_t addr) {
    asm volatile("ldmatrix.sync.aligned.m8n8.x4.shared.b16 {%0,%1,%2,%3}, [%4];\n"
                 : "=r"(r[0]), "=r"(r[1]), "=r"(r[2]), "=r"(r[3]) : "r"(addr));
}
__device__ __forceinline__ void ldsm_x4_t(uint32_t* r, uint32_t addr) {
    asm volatile("ldmatrix.sync.aligned.m8n8.x4.trans.shared.b16 {%0,%1,%2,%3}, [%4];\n"
                 : "=r"(r[0]), "=r"(r[1]), "=r"(r[2]), "=r"(r[3]) : "r"(addr));
}
__device__ __forceinline__ void cpa16(uint32_t dst, const void* src) {
    asm volatile("cp.async.cg.shared.global [%0], [%1], 16;\n" :: "r"(dst), "l"(src));
}
#define CP_COMMIT() asm volatile("cp.async.commit_group;\n" ::: "memory")
#define CP_WAIT0()  asm volatile("cp.async.wait_group 0;\n" ::: "memory")

// ---------------- main conv kernel ----------------
// CTA tile: M = 128 px (2 rows x 64), N = 128 oc. 4 warps_n x 2 warps_m.
// Xs: [4 rows][66 cols] pixel-rows of 64 ic (stride 144B, conflict-free).
// Bs: 2 x [64 ic][128 oc] (stride 272B, conflict-free).
#define XS_BYTES 38016              // 264 * 144
#define BS_BYTES 17408              // 64 * 272
#define SMEM_BYTES (XS_BYTES + 2 * BS_BYTES)   // 72832

__global__ void __launch_bounds__(256, 2)
k_conv(const float* __restrict__ noise, const float* __restrict__ nzw,
       const float* __restrict__ bias, float* __restrict__ out) {
    extern __shared__ __half smemh[];
    const uint32_t xs_b = (uint32_t)__cvta_generic_to_shared(smemh);
    const uint32_t bs_b = xs_b + XS_BYTES;

    const int b = blockIdx.z, mt = blockIdx.y, nt = blockIdx.x;
    const int tid = threadIdx.x, lane = tid & 31, wid = tid >> 5;
    const int warp_m = wid & 1;
    const int warp_n = wid >> 1;
    const int y0 = mt * 2;

    const __half* xp_b = g_xp + (((size_t)b * 66 + y0) * 66) * CCH;
    const __half* wm_b = g_wmod + (size_t)b * KTAP * CCH * CCH + (size_t)nt * 128;

    // precomputed prefetch lanes
    const int brow = tid >> 4, bseg = tid & 15;         // B: 64 rows x 16 segs
    const uint32_t bdst0 = bs_b + (uint32_t)(brow * 272 + bseg * 16);
    const size_t  bsrc0 = (size_t)brow * CCH + bseg * 8;

    float acc[4][4][4];
#pragma unroll
    for (int i = 0; i < 4; i++)
#pragma unroll
        for (int j = 0; j < 4; j++)
#pragma unroll
            for (int k = 0; k < 4; k++) acc[i][j][k] = 0.f;

    const int off_m = ((lane >> 3) & 1) * 8 + (lane & 7);
    const int off_k = (lane >> 4) * 8;
    // B ldmatrix x4.trans lane base: rows = k (lane&15), col group = n+8*(lane>>4)
    const uint32_t b_lane = bs_b + (uint32_t)((lane & 15) * 272) +
                            (uint32_t)((warp_n * 32 + (lane >> 4) * 8) * 2);

    for (int kc = 0; kc < 8; kc++) {
        __syncthreads();
        // X chunk: 264 pixel-rows x 64 ic
        {
            const __half* src = xp_b + kc * 64;
            for (int s = tid; s < 264 * 8; s += 256) {
                int row = s >> 3, seg = s & 7;
                cpa16(xs_b + (uint32_t)(row * 144 + seg * 16),
                      src + (size_t)row * CCH + seg * 8);
            }
        }
        // B chunk tap 0 -> buffer 0
        {
            const __half* src = wm_b + ((size_t)kc * 64) * CCH + bsrc0;
#pragma unroll
            for (int j = 0; j < 4; j++)
                cpa16(bdst0 + (uint32_t)(j * 16 * 272), src + (size_t)j * 16 * CCH);
        }
        CP_COMMIT();
        CP_WAIT0();
        __syncthreads();

        for (int t = 0; t < KTAP; t++) {
            int buf = t & 1;
            if (t < 8) {   // prefetch next tap into other buffer
                const __half* src = wm_b + ((size_t)(t + 1) * CCH + kc * 64) * CCH + bsrc0;
                uint32_t dst = bdst0 + (uint32_t)((buf ^ 1) * BS_BYTES);
#pragma unroll
                for (int j = 0; j < 4; j++)
                    cpa16(dst + (uint32_t)(j * 16 * 272), src + (size_t)j * 16 * CCH);
                CP_COMMIT();
            }

            int dy = t / 3, dx = t - dy * 3;
            uint32_t A0 = xs_b +
                (uint32_t)((((warp_m + dy) * 66) + off_m + dx) * 144 + off_k * 2);
            uint32_t Bb = b_lane + (uint32_t)(buf * BS_BYTES);

#pragma unroll
            for (int k16 = 0; k16 < 4; k16++) {
                uint32_t a[4][4];
#pragma unroll
                for (int mf = 0; mf < 4; mf++)
                    ldsm_x4(a[mf], A0 + mf * 2304 + k16 * 32);
#pragma unroll
                for (int g = 0; g < 2; g++) {
                    uint32_t bf[4];
                    ldsm_x4_t(bf, Bb + k16 * (16 * 272) + g * 32);
#pragma unroll
                    for (int mf = 0; mf < 4; mf++) {
                        mma16816(acc[mf][g * 2],     a[mf], bf[0], bf[1]);
                        mma16816(acc[mf][g * 2 + 1], a[mf], bf[2], bf[3]);
                    }
                }
            }

            if (t < 8) { CP_WAIT0(); __syncthreads(); }
        }
    }

    // -------- epilogue --------
    const int g = lane >> 2, tq = lane & 3;
    const int yrow = y0 + warp_m;
    const float* nrow = noise + (size_t)b * NPIX + (size_t)yrow * HW;
    float nzv[4][2];
#pragma unroll
    for (int mf = 0; mf < 4; mf++) {
        nzv[mf][0] = nrow[mf * 16 + g];
        nzv[mf][1] = nrow[mf * 16 + g + 8];
    }
    const size_t outb = (size_t)b * CCH * NPIX;
#pragma unroll
    for (int nf = 0; nf < 4; nf++) {
        int oc = nt * 128 + warp_n * 32 + nf * 8 + tq * 2;
        float nw0 = nzw[oc], nw1 = nzw[oc + 1];
        float bi0 = bias[oc], bi1 = bias[oc + 1];
        float* o0 = out + outb + (size_t)oc * NPIX + (size_t)yrow * HW;
#pragma unroll
        for (int mf = 0; mf < 4; mf++) {
            int x0 = mf * 16 + g;
            float v;
            v = acc[mf][nf][0] + nw0 * nzv[mf][0] + bi0; o0[x0]            = v > 0.f ? v : 0.2f * v;
            v = acc[mf][nf][1] + nw1 * nzv[mf][0] + bi1; o0[NPIX + x0]     = v > 0.f ? v : 0.2f * v;
            v = acc[mf][nf][2] + nw0 * nzv[mf][1] + bi0; o0[x0 + 8]        = v > 0.f ? v : 0.2f * v;
            v = acc[mf][nf][3] + nw1 * nzv[mf][1] + bi1; o0[NPIX + x0 + 8] = v > 0.f ? v : 0.2f * v;
        }
    }
}

// ---------------- launcher ----------------
extern "C" void kernel_launch(void* const* d_in, const int* in_sizes, int n_in,
                              void* d_out, int out_size) {
    const float* x     = (const float*)d_in[0];
    const float* w     = (const float*)d_in[1];
    const float* sw    = (const float*)d_in[2];
    const float* sb    = (const float*)d_in[3];
    const float* cw    = (const float*)d_in[4];
    const float* nzw   = (const float*)d_in[5];
    const float* bias  = (const float*)d_in[6];
    const float* noise = (const float*)d_in[7];
    float* out = (float*)d_out;

    cudaFuncSetAttribute((const void*)k_conv,
                         cudaFuncAttributeMaxDynamicSharedMemorySize, SMEM_BYTES);

    k_style<<<NB * CCH / 8, 256>>>(w, sw, sb);
    k_prepw<<<dim3(16, 16), dim3(32, 8)>>>(cw);
    k_sigma<<<NB * CCH / 8, 256>>>();
    k_wmod<<<NB * CCH, CCH>>>();
    k_borders<<<dim3(260, NB), 128>>>();
    k_xpose<<<NB * HW, 256>>>(x);
    k_conv<<<dim3(4, 32, NB), 256, SMEM_BYTES>>>(noise, nzw, bias, out);
}